// round 16
// baseline (speedup 1.0000x reference)
#include <cuda_runtime.h>
#include <cstdint>

#define MAXB 8
#define MAXN 2048

// ---------------- scratch ----------------
__device__ float g_embnP[MAXB * MAXN * 64];   // emb_n, node-major, phi f (knn)
__device__ float g_Ep   [MAXB * MAXN * 64];   // emb,   node-major, phi f
__device__ float g_EjF  [MAXB * MAXN * 64];   // emb  gemm1-B fragments, tile-major (RNA tf32)
__device__ float g_EnF  [MAXB * MAXN * 64];   // embn gemm2-B fragments, tile-major (RNA tf32)
__device__ float g_sq   [MAXB * MAXN];
__device__ float g_deg  [MAXB * MAXN];
__device__ float g_opadjP[MAXB * MAXN * 64];
__device__ float g_part [MAXB * 8 * 128];
__device__ uint4 g_W1f  [128 * 32];
__device__ uint4 g_W2f  [128 * 32];

__device__ __forceinline__ int phi(int k) {
    int r = k & 7;
    return (k & ~7) | (((r & 3) << 1) | (r >> 2));
}
__device__ __forceinline__ uint32_t f2tf(float x) {
    uint32_t r;
    asm("cvt.rna.tf32.f32 %0, %1;" : "=r"(r) : "f"(x));
    return r;
}
__device__ __forceinline__ void split_tf(float v, uint32_t& hi, uint32_t& lo) {
    hi = f2tf(v);
    lo = f2tf(v - __uint_as_float(hi));
}
__device__ __forceinline__ void cpa16(uint32_t saddr, const void* gaddr) {
    asm volatile("cp.async.cg.shared.global [%0], [%1], 16;\n" :: "r"(saddr), "l"(gaddr));
}

#define MMA_TF32(d, a0, a1, a2, a3, b0, b1)                                  \
    asm volatile(                                                            \
        "mma.sync.aligned.m16n8k8.row.col.f32.tf32.tf32.f32 "                \
        "{%0,%1,%2,%3}, {%4,%5,%6,%7}, {%8,%9}, {%0,%1,%2,%3};\n"            \
        : "+f"(d[0]), "+f"(d[1]), "+f"(d[2]), "+f"(d[3])                     \
        : "r"(a0), "r"(a1), "r"(a2), "r"(a3), "r"(b0), "r"(b1))

// ---------------- Kernel 1a: partial sums (grid B x 10) + fused weight prep ----------------
__global__ __launch_bounds__(256) void kstat1(const float* __restrict__ emb,
                                              const float* __restrict__ W1,
                                              const float* __restrict__ W2, int N)
{
    const int b = blockIdx.x, slice = blockIdx.y;
    const int t = threadIdx.x;

    if (slice >= 8) {
        const int id = (b * 2 + (slice - 8)) * 256 + t;
        const int lane = id & 31, frag = id >> 5;
        const int ks = frag & 15, nt = frag >> 4;
        const int g = lane >> 2, tg = lane & 3;
        const int n = nt * 8 + g;
        const int k0 = ks * 8 + tg, k1 = k0 + 4;
        uint32_t h0, l0, h1, l1;
        split_tf(W1[k0 * 64 + n], h0, l0);
        split_tf(W1[k1 * 64 + n], h1, l1);
        g_W1f[frag * 32 + lane] = make_uint4(h0, h1, l0, l1);
        split_tf(W2[k0 * 64 + n], h0, l0);
        split_tf(W2[k1 * 64 + n], h1, l1);
        g_W2f[frag * 32 + lane] = make_uint4(h0, h1, l0, l1);
        return;
    }

    __shared__ float ssum[4][64], ssq[4][64];
    const int f = t & 63, g = t >> 6;
    const int r0 = slice * (N / 8), r1 = r0 + N / 8;
    const float* E = emb + (size_t)b * N * 64;
    float s = 0.f, q = 0.f;
    for (int i = r0 + g; i < r1; i += 4) {
        float v = E[(size_t)i * 64 + f];
        s += v; q += v * v;
    }
    ssum[g][f] = s; ssq[g][f] = q;
    __syncthreads();
    if (t < 64) {
        g_part[(b * 8 + slice) * 128 + t]      = ssum[0][t] + ssum[1][t] + ssum[2][t] + ssum[3][t];
        g_part[(b * 8 + slice) * 128 + 64 + t] = ssq[0][t]  + ssq[1][t]  + ssq[2][t]  + ssq[3][t];
    }
}

// ---------------- Kernel 1c: stats-finish + normalize + fragment-major copies + sq ----------------
__global__ __launch_bounds__(256) void knorm2(const float* __restrict__ emb,
                                              const int* __restrict__ nb, int N)
{
    __shared__ float etile[8][65];
    __shared__ float ntile[8][65];
    __shared__ float smean[64], srstd[64];

    const int t = threadIdx.x, w = t >> 5, lane = t & 31;
    const int row = blockIdx.x * 8 + w;
    const int b = row / N, j = row - b * N;

    if (t < 64) {
        float S = 0.f, Q = 0.f;
        #pragma unroll
        for (int s = 0; s < 8; s++) {
            S += g_part[(b * 8 + s) * 128 + t];
            Q += g_part[(b * 8 + s) * 128 + 64 + t];
        }
        float cnt  = fmaxf((float)nb[b], 1.f);
        float mean = S / cnt;
        float var  = fmaxf(Q / cnt - mean * mean, 0.f);
        smean[t] = mean;
        srstd[t] = rsqrtf(var + 1e-5f);
    }
    __syncthreads();

    const float m0 = smean[lane];
    const float m1 = smean[lane + 32];
    const float r0 = srstd[lane];
    const float r1 = srstd[lane + 32];

    const float* E = emb + (size_t)row * 64;
    float e0 = E[lane], e1 = E[lane + 32];
    float m = (j < nb[b]) ? 1.f : 0.f;
    float n0 = (e0 - m0) * r0 * m;
    float n1 = (e1 - m1) * r1 * m;

    const int pf0 = phi(lane), pf1 = phi(lane + 32);
    g_Ep   [(size_t)row * 64 + pf0] = e0;
    g_Ep   [(size_t)row * 64 + pf1] = e1;
    g_embnP[(size_t)row * 64 + pf0] = n0;
    g_embnP[(size_t)row * 64 + pf1] = n1;
    etile[w][lane] = e0;  etile[w][lane + 32] = e1;
    ntile[w][lane] = n0;  ntile[w][lane + 32] = n1;

    float sq = e0 * e0 + e1 * e1;
    #pragma unroll
    for (int o = 16; o; o >>= 1) sq += __shfl_down_sync(0xffffffffu, sq, o);
    if (lane == 0) g_sq[row] = sq;

    __syncthreads();

    const int j0 = (blockIdx.x * 8) % N;
    const int b0 = (blockIdx.x * 8) / N;
    const int nbk = (j0 & 63) >> 3;
    const size_t tbase = ((size_t)(b0 * (N >> 6) + (j0 >> 6))) * 4096;

    #pragma unroll
    for (int it = 0; it < 2; it++) {
        const int idx = t + it * 256;
        const int seg = idx >> 6;
        const int sl  = idx & 63;
        const int lp = sl >> 1, half = sl & 1;
        const int g = lp >> 2, q = lp & 3;
        g_EjF[tbase + (size_t)(nbk * 8 + seg) * 64 + sl] =
            __uint_as_float(f2tf(etile[g][seg * 8 + half * 4 + q]));
        g_EnF[tbase + (size_t)(seg * 8 + nbk) * 64 + sl] =
            __uint_as_float(f2tf(ntile[half * 4 + q][seg * 8 + g]));
    }
}

// ---------------- Kernel 2: fused Gram -> eltwise -> adj/deg -> SpMM (R13 verbatim) ----------------
#define SSS 72
#define OFF_EJ  0u
#define OFF_EN  32768u
#define OFF_SS  65536u
#define OFF_SQ  (65536u + 64u * SSS * 4u)
#define OFF_DG  (OFF_SQ + 512u)
#define SMEM_KADJ (OFF_DG + 256u)

__global__ __launch_bounds__(256, 2) void kadj(
    const float* __restrict__ adj_in,
    const int* __restrict__ nb, const float* __restrict__ sigma_p,
    const float* __restrict__ cw, float* __restrict__ adj_out, int N)
{
    extern __shared__ char smc[];
    uint32_t* sS   = (uint32_t*)(smc + OFF_SS);
    float*    ssqj = (float*)(smc + OFF_SQ);
    float*    sdeg = (float*)(smc + OFF_DG);

    const int b = blockIdx.y;
    const int ibase = blockIdx.x * 64;
    const int t = threadIdx.x;
    const int w = t >> 5, lane = t & 31;
    const int rowb = (w >> 1) * 16, colb = (w & 1) * 32;
    const int g = lane >> 2, tg = lane & 3;
    const int p0 = (((2 * tg) & 3) << 1) | ((2 * tg) >> 2);
    const int p1 = (((2 * tg + 1) & 3) << 1) | ((2 * tg + 1) >> 2);

    const float inv_sigma = 1.0f / sigma_p[0];
    const float w0 = cw[0], w1 = cw[1];
    const int nbv = nb[b];

    const float* Ep   = g_Ep    + (size_t)b * N * 64;
    const float* SQ   = g_sq    + b * N;
    const float* Ain  = adj_in  + (size_t)b * N * N;
    float*       Aout = adj_out + (size_t)b * N * N;

    uint32_t u_base;
    asm("{ .reg .u64 t; cvta.to.shared.u64 t, %1; cvt.u32.u64 %0, t; }"
        : "=r"(u_base) : "l"(smc));

    const int gi0 = ibase + rowb + g;
    const int gi1 = gi0 + 8;

    auto stage = [&](int pb, int jt) {
        const size_t tIdx = (size_t)(b * (N >> 6) + (jt >> 6)) * 4096;
        const float* srcEj = g_EjF + tIdx;
        const float* srcEn = g_EnF + tIdx;
        #pragma unroll
        for (int k = 0; k < 4; k++) {
            const int c = t + k * 256;
            cpa16(u_base + OFF_EJ + pb * 16384u + c * 16u, srcEj + c * 4);
            cpa16(u_base + OFF_EN + pb * 16384u + c * 16u, srcEn + c * 4);
        }
        if (t < 16)
            cpa16(u_base + OFF_SQ + pb * 256u + t * 16u, &SQ[jt + t * 4]);
    };

    stage(0, 0);
    asm volatile("cp.async.commit_group;\n");

    uint32_t aF[8][4];
    #pragma unroll
    for (int ks = 0; ks < 8; ks++) {
        float2 q0 = *(const float2*)&Ep[(size_t)gi0 * 64 + ks * 8 + 2 * tg];
        float2 q1 = *(const float2*)&Ep[(size_t)gi1 * 64 + ks * 8 + 2 * tg];
        aF[ks][0] = f2tf(q0.x);
        aF[ks][1] = f2tf(q1.x);
        aF[ks][2] = f2tf(q0.y);
        aF[ks][3] = f2tf(q1.y);
    }
    const float sqi0 = SQ[gi0];
    const float sqi1 = SQ[gi1];
    if (t < 64) sdeg[t] = 0.f;
    const float mi0 = (gi0 < nbv) ? 1.f : 0.f;
    const float mi1 = (gi1 < nbv) ? 1.f : 0.f;

    float opa[4][4];
    #pragma unroll
    for (int n = 0; n < 4; n++)
        #pragma unroll
        for (int k = 0; k < 4; k++) opa[n][k] = 0.f;
    float dg0 = 0.f, dg1 = 0.f;

    asm volatile("cp.async.wait_group 0;\n");
    __syncthreads();

    int pb = 0;
    for (int jt = 0; jt < N; jt += 64, pb ^= 1) {
        if (jt + 64 < N) stage(pb ^ 1, jt + 64);
        asm volatile("cp.async.commit_group;\n");

        float2 a01[4], a23[4];
        #pragma unroll
        for (int nt = 0; nt < 4; nt++) {
            const int gj = jt + colb + nt * 8 + 2 * tg;
            a01[nt] = *(const float2*)&Ain[(size_t)gi0 * N + gj];
            a23[nt] = *(const float2*)&Ain[(size_t)gi1 * N + gj];
        }

        const uint2* Ej = (const uint2*)(smc + OFF_EJ + pb * 16384u);
        const uint2* En = (const uint2*)(smc + OFF_EN + pb * 16384u);
        const float* sqj = ssqj + pb * 64;

        float S[4][4];
        #pragma unroll
        for (int n = 0; n < 4; n++)
            #pragma unroll
            for (int k = 0; k < 4; k++) S[n][k] = 0.f;

        #pragma unroll
        for (int nt = 0; nt < 4; nt++) {
            const int jb = (w & 1) * 4 + nt;
            #pragma unroll
            for (int ks = 0; ks < 8; ks++) {
                uint2 bv = Ej[(jb * 8 + ks) * 32 + lane];
                MMA_TF32(S[nt], aF[ks][0], aF[ks][1], aF[ks][2], aF[ks][3], bv.x, bv.y);
            }
        }

        #pragma unroll
        for (int nt = 0; nt < 4; nt++) {
            const int jl = colb + nt * 8 + 2 * tg;
            const int gj = jt + jl;
            const float sqj0 = sqj[jl], sqj1 = sqj[jl + 1];
            const float mj0 = (gj     < nbv) ? 1.f : 0.f;
            const float mj1 = (gj + 1 < nbv) ? 1.f : 0.f;

            float v00 = (w0 * a01[nt].x + w1 * __expf(-fmaxf(sqi0 + sqj0 - 2.f * S[nt][0], 0.f) * inv_sigma)) * (mi0 * mj0);
            float v01 = (w0 * a01[nt].y + w1 * __expf(-fmaxf(sqi0 + sqj1 - 2.f * S[nt][1], 0.f) * inv_sigma)) * (mi0 * mj1);
            float v10 = (w0 * a23[nt].x + w1 * __expf(-fmaxf(sqi1 + sqj0 - 2.f * S[nt][2], 0.f) * inv_sigma)) * (mi1 * mj0);
            float v11 = (w0 * a23[nt].y + w1 * __expf(-fmaxf(sqi1 + sqj1 - 2.f * S[nt][3], 0.f) * inv_sigma)) * (mi1 * mj1);

            dg0 += v00 + v01;
            dg1 += v10 + v11;

            *(float2*)&Aout[(size_t)gi0 * N + gj] = make_float2(v00, v01);
            *(float2*)&Aout[(size_t)gi1 * N + gj] = make_float2(v10, v11);

            const int cb = colb + nt * 8;
            sS[(rowb + g)     * SSS + cb + p0] = f2tf(v00);
            sS[(rowb + g)     * SSS + cb + p1] = f2tf(v01);
            sS[(rowb + g + 8) * SSS + cb + p0] = f2tf(v10);
            sS[(rowb + g + 8) * SSS + cb + p1] = f2tf(v11);
        }
        asm volatile("bar.sync %0, 64;" :: "r"(1 + (w >> 1)) : "memory");

        #pragma unroll
        for (int ks = 0; ks < 8; ks++) {
            uint2 A02 = *(const uint2*)&sS[(rowb + g)     * SSS + ks * 8 + 2 * tg];
            uint2 A13 = *(const uint2*)&sS[(rowb + g + 8) * SSS + ks * 8 + 2 * tg];
            #pragma unroll
            for (int nt = 0; nt < 4; nt++) {
                const int fb = (w & 1) * 4 + nt;
                uint2 bv = En[(fb * 8 + ks) * 32 + lane];
                MMA_TF32(opa[nt], A02.x, A13.x, A02.y, A13.y, bv.x, bv.y);
            }
        }

        asm volatile("cp.async.wait_group 0;\n");
        __syncthreads();
    }

    dg0 += __shfl_xor_sync(0xffffffffu, dg0, 1);
    dg0 += __shfl_xor_sync(0xffffffffu, dg0, 2);
    dg1 += __shfl_xor_sync(0xffffffffu, dg1, 1);
    dg1 += __shfl_xor_sync(0xffffffffu, dg1, 2);
    if (tg == 0) {
        atomicAdd(&sdeg[rowb + g], dg0);
        atomicAdd(&sdeg[rowb + g + 8], dg1);
    }
    __syncthreads();
    if (t < 64) g_deg[b * N + ibase + t] = sdeg[t];

    #pragma unroll
    for (int nt = 0; nt < 4; nt++) {
        const int f0 = colb + nt * 8;
        g_opadjP[(size_t)(b * N + gi0) * 64 + f0 + p0] = opa[nt][0];
        g_opadjP[(size_t)(b * N + gi0) * 64 + f0 + p1] = opa[nt][1];
        g_opadjP[(size_t)(b * N + gi1) * 64 + f0 + p0] = opa[nt][2];
        g_opadjP[(size_t)(b * N + gi1) * 64 + f0 + p1] = opa[nt][3];
    }
}

// ---------------- Kernel 3: fused 2-stage MLP, weights via LDG from L2 ----------------
// 64 nodes/CTA (grid 256), 8 warps: rows (w>>1)*16.., n-cols (w&1)*32..
#define SX 136

__global__ __launch_bounds__(256, 4) void knn(
    const float* __restrict__ embnP, const float* __restrict__ opadjP,
    const float* __restrict__ deg,   const float* __restrict__ Ep,
    const uint4* __restrict__ W1f,   const float* __restrict__ b1,
    const uint4* __restrict__ W2f,   const float* __restrict__ b2,
    float* __restrict__ out)
{
    extern __shared__ float smn[];
    float* sx  = smn;                 // [64][SX]
    float* sb1 = sx + 64 * SX;
    float* sb2 = sb1 + 64;

    const int t = threadIdx.x;
    const int w = t >> 5, lane = t & 31;
    const int g = lane >> 2, tg = lane & 3;
    const int rowb = (w >> 1) * 16, colb = (w & 1) * 32;
    const int node0 = blockIdx.x * 64;
    const int p0 = (((2 * tg) & 3) << 1) | ((2 * tg) >> 2);
    const int p1 = (((2 * tg + 1) & 3) << 1) | ((2 * tg + 1) >> 2);

    if (t < 64) { sb1[t] = b1[t]; sb2[t] = b2[t]; }

    // stage x1 = [deg*embn (phi), opadj (phi)]
    for (int idx = t; idx < 1024; idx += 256) {
        const int node = idx >> 4, c = (idx & 15) << 2;
        const float dgv = deg[node0 + node];
        float4 v = *(const float4*)&embnP[(size_t)(node0 + node) * 64 + c];
        v.x *= dgv; v.y *= dgv; v.z *= dgv; v.w *= dgv;
        *(float4*)&sx[node * SX + c] = v;
        *(float4*)&sx[node * SX + 64 + c] =
            *(const float4*)&opadjP[(size_t)(node0 + node) * 64 + c];
    }
    __syncthreads();

    // ---- stage 1: upd = x1 @ W1  (weights via LDG, split hh+lh+hl) ----
    float acc1[4][4];
    #pragma unroll
    for (int n = 0; n < 4; n++)
        #pragma unroll
        for (int k = 0; k < 4; k++) acc1[n][k] = 0.f;

    #pragma unroll
    for (int ks = 0; ks < 16; ks++) {
        float2 A0 = *(const float2*)&sx[(rowb + g)     * SX + ks * 8 + 2 * tg];
        float2 A1 = *(const float2*)&sx[(rowb + g + 8) * SX + ks * 8 + 2 * tg];
        uint32_t ah[4], al[4];
        split_tf(A0.x, ah[0], al[0]);
        split_tf(A1.x, ah[1], al[1]);
        split_tf(A0.y, ah[2], al[2]);
        split_tf(A1.y, ah[3], al[3]);
        #pragma unroll
        for (int nt = 0; nt < 4; nt++) {
            const int nf = (colb >> 3) + nt;
            uint4 wv = __ldg(&W1f[(nf * 16 + ks) * 32 + lane]);
            MMA_TF32(acc1[nt], ah[0], ah[1], ah[2], ah[3], wv.x, wv.y);
            MMA_TF32(acc1[nt], al[0], al[1], al[2], al[3], wv.x, wv.y);
            MMA_TF32(acc1[nt], ah[0], ah[1], ah[2], ah[3], wv.z, wv.w);
        }
    }
    __syncthreads();   // all warps done reading x1

    // build x2 = [emb_in (phi), upd+b1 (phi)]
    for (int idx = t; idx < 512; idx += 256) {
        const int node = idx >> 3, c = (idx & 7) << 3;
        *(float4*)&sx[node * SX + c]     = *(const float4*)&Ep[(size_t)(node0 + node) * 64 + c];
        *(float4*)&sx[node * SX + c + 4] = *(const float4*)&Ep[(size_t)(node0 + node) * 64 + c + 4];
    }
    #pragma unroll
    for (int nt = 0; nt < 4; nt++) {
        const int f0 = colb + nt * 8 + 2 * tg;
        const int base = 64 + colb + nt * 8;
        sx[(rowb + g)     * SX + base + p0] = acc1[nt][0] + sb1[f0];
        sx[(rowb + g)     * SX + base + p1] = acc1[nt][1] + sb1[f0 + 1];
        sx[(rowb + g + 8) * SX + base + p0] = acc1[nt][2] + sb1[f0];
        sx[(rowb + g + 8) * SX + base + p1] = acc1[nt][3] + sb1[f0 + 1];
    }
    __syncthreads();

    // ---- stage 2: out = relu(x2 @ W2 + b2) ----
    float acc2[4][4];
    #pragma unroll
    for (int n = 0; n < 4; n++)
        #pragma unroll
        for (int k = 0; k < 4; k++) acc2[n][k] = 0.f;

    #pragma unroll
    for (int ks = 0; ks < 16; ks++) {
        float2 A0 = *(const float2*)&sx[(rowb + g)     * SX + ks * 8 + 2 * tg];
        float2 A1 = *(const float2*)&sx[(rowb + g + 8) * SX + ks * 8 + 2 * tg];
        uint32_t ah[4], al[4];
        split_tf(A0.x, ah[0], al[0]);
        split_tf(A1.x, ah[1], al[1]);
        split_tf(A0.y, ah[2], al[2]);
        split_tf(A1.y, ah[3], al[3]);
        #pragma unroll
        for (int nt = 0; nt < 4; nt++) {
            const int nf = (colb >> 3) + nt;
            uint4 wv = __ldg(&W2f[(nf * 16 + ks) * 32 + lane]);
            MMA_TF32(acc2[nt], ah[0], ah[1], ah[2], ah[3], wv.x, wv.y);
            MMA_TF32(acc2[nt], al[0], al[1], al[2], al[3], wv.x, wv.y);
            MMA_TF32(acc2[nt], ah[0], ah[1], ah[2], ah[3], wv.z, wv.w);
        }
    }

    #pragma unroll
    for (int nt = 0; nt < 4; nt++) {
        const int f0 = colb + nt * 8 + 2 * tg;
        float o00 = fmaxf(acc2[nt][0] + sb2[f0],     0.f);
        float o01 = fmaxf(acc2[nt][1] + sb2[f0 + 1], 0.f);
        float o10 = fmaxf(acc2[nt][2] + sb2[f0],     0.f);
        float o11 = fmaxf(acc2[nt][3] + sb2[f0 + 1], 0.f);
        *(float2*)&out[(size_t)(node0 + rowb + g)     * 64 + f0] = make_float2(o00, o01);
        *(float2*)&out[(size_t)(node0 + rowb + g + 8) * 64 + f0] = make_float2(o10, o11);
    }
}

// ---------------- launch ----------------
extern "C" void kernel_launch(void* const* d_in, const int* in_sizes, int n_in,
                              void* d_out, int out_size)
{
    const float* emb_in = (const float*)d_in[0];
    const float* adj_in = (const float*)d_in[1];
    // d_in[2] adj_mask: unused (recomputed from batch_nb_nodes)
    const int*   nbp    = (const int*)d_in[3];
    const float* sigma  = (const float*)d_in[4];
    const float* cw     = (const float*)d_in[5];
    const float* convW  = (const float*)d_in[6];
    const float* convb  = (const float*)d_in[7];
    const float* nuW    = (const float*)d_in[8];
    const float* nub    = (const float*)d_in[9];

    const int B = in_sizes[3];
    const int N = in_sizes[0] / (B * 64);

    float* out_emb = (float*)d_out;                    // (B,N,64)
    float* out_adj = out_emb + (size_t)B * N * 64;     // (B,N,N)

    float *p_embnP, *p_opadjP, *p_deg, *p_Ep;
    uint4 *p_W1f, *p_W2f;
    cudaGetSymbolAddress((void**)&p_embnP,  g_embnP);
    cudaGetSymbolAddress((void**)&p_opadjP, g_opadjP);
    cudaGetSymbolAddress((void**)&p_deg,    g_deg);
    cudaGetSymbolAddress((void**)&p_Ep,     g_Ep);
    cudaGetSymbolAddress((void**)&p_W1f,    g_W1f);
    cudaGetSymbolAddress((void**)&p_W2f,    g_W2f);

    kstat1<<<dim3(B, 10), 256>>>(emb_in, convW, nuW, N);
    knorm2<<<(B * N) / 8, 256>>>(emb_in, nbp, N);

    cudaFuncSetAttribute(kadj, cudaFuncAttributeMaxDynamicSharedMemorySize, (int)SMEM_KADJ);
    kadj<<<dim3(N / 64, B), 256, SMEM_KADJ>>>(adj_in, nbp, sigma, cw, out_adj, N);

    const size_t smemNN = (size_t)(64 * SX + 128) * sizeof(float);
    cudaFuncSetAttribute(knn, cudaFuncAttributeMaxDynamicSharedMemorySize, (int)smemNN);
    knn<<<(B * N) / 64, 256, smemNN>>>(p_embnP, p_opadjP, p_deg, p_Ep,
                                       p_W1f, convb, p_W2f, nub, out_emb);
}

// round 17
// speedup vs baseline: 1.0582x; 1.0582x over previous
#include <cuda_runtime.h>
#include <cstdint>

#define MAXB 8
#define MAXN 2048

// ---------------- scratch ----------------
__device__ float g_embnP[MAXB * MAXN * 64];   // emb_n, node-major, phi f
__device__ float g_Ep   [MAXB * MAXN * 64];   // emb,   node-major, phi f
__device__ float g_EjF  [MAXB * MAXN * 64];   // emb  gemm1-B fragments, tile-major (RNA tf32)
__device__ float g_EnF  [MAXB * MAXN * 64];   // embn gemm2-B fragments, tile-major (RNA tf32)
__device__ float g_sq   [MAXB * MAXN];
__device__ float g_part [MAXB * 8 * 128];
__device__ uint4 g_W1f  [128 * 32];
__device__ uint4 g_W2f  [128 * 32];

__device__ __forceinline__ int phi(int k) {
    int r = k & 7;
    return (k & ~7) | (((r & 3) << 1) | (r >> 2));
}
__device__ __forceinline__ uint32_t f2tf(float x) {
    uint32_t r;
    asm("cvt.rna.tf32.f32 %0, %1;" : "=r"(r) : "f"(x));
    return r;
}
__device__ __forceinline__ void split_tf(float v, uint32_t& hi, uint32_t& lo) {
    hi = f2tf(v);
    lo = f2tf(v - __uint_as_float(hi));
}
__device__ __forceinline__ void cpa16(uint32_t saddr, const void* gaddr) {
    asm volatile("cp.async.cg.shared.global [%0], [%1], 16;\n" :: "r"(saddr), "l"(gaddr));
}

#define MMA_TF32(d, a0, a1, a2, a3, b0, b1)                                  \
    asm volatile(                                                            \
        "mma.sync.aligned.m16n8k8.row.col.f32.tf32.tf32.f32 "                \
        "{%0,%1,%2,%3}, {%4,%5,%6,%7}, {%8,%9}, {%0,%1,%2,%3};\n"            \
        : "+f"(d[0]), "+f"(d[1]), "+f"(d[2]), "+f"(d[3])                     \
        : "r"(a0), "r"(a1), "r"(a2), "r"(a3), "r"(b0), "r"(b1))

// ---------------- Kernel 1a: partial sums (grid B x 10) + fused weight prep ----------------
__global__ __launch_bounds__(256) void kstat1(const float* __restrict__ emb,
                                              const float* __restrict__ W1,
                                              const float* __restrict__ W2, int N)
{
    const int b = blockIdx.x, slice = blockIdx.y;
    const int t = threadIdx.x;

    if (slice >= 8) {
        const int id = (b * 2 + (slice - 8)) * 256 + t;
        const int lane = id & 31, frag = id >> 5;
        const int ks = frag & 15, nt = frag >> 4;
        const int g = lane >> 2, tg = lane & 3;
        const int n = nt * 8 + g;
        const int k0 = ks * 8 + tg, k1 = k0 + 4;
        uint32_t h0, l0, h1, l1;
        split_tf(W1[k0 * 64 + n], h0, l0);
        split_tf(W1[k1 * 64 + n], h1, l1);
        g_W1f[frag * 32 + lane] = make_uint4(h0, h1, l0, l1);
        split_tf(W2[k0 * 64 + n], h0, l0);
        split_tf(W2[k1 * 64 + n], h1, l1);
        g_W2f[frag * 32 + lane] = make_uint4(h0, h1, l0, l1);
        return;
    }

    __shared__ float ssum[4][64], ssq[4][64];
    const int f = t & 63, g = t >> 6;
    const int r0 = slice * (N / 8), r1 = r0 + N / 8;
    const float* E = emb + (size_t)b * N * 64;
    float s = 0.f, q = 0.f;
    for (int i = r0 + g; i < r1; i += 4) {
        float v = E[(size_t)i * 64 + f];
        s += v; q += v * v;
    }
    ssum[g][f] = s; ssq[g][f] = q;
    __syncthreads();
    if (t < 64) {
        g_part[(b * 8 + slice) * 128 + t]      = ssum[0][t] + ssum[1][t] + ssum[2][t] + ssum[3][t];
        g_part[(b * 8 + slice) * 128 + 64 + t] = ssq[0][t]  + ssq[1][t]  + ssq[2][t]  + ssq[3][t];
    }
}

// ---------------- Kernel 1c: stats-finish + normalize + fragment-major copies + sq ----------------
__global__ __launch_bounds__(256) void knorm2(const float* __restrict__ emb,
                                              const int* __restrict__ nb, int N)
{
    __shared__ float etile[8][65];
    __shared__ float ntile[8][65];
    __shared__ float smean[64], srstd[64];

    const int t = threadIdx.x, w = t >> 5, lane = t & 31;
    const int row = blockIdx.x * 8 + w;
    const int b = row / N, j = row - b * N;

    if (t < 64) {
        float S = 0.f, Q = 0.f;
        #pragma unroll
        for (int s = 0; s < 8; s++) {
            S += g_part[(b * 8 + s) * 128 + t];
            Q += g_part[(b * 8 + s) * 128 + 64 + t];
        }
        float cnt  = fmaxf((float)nb[b], 1.f);
        float mean = S / cnt;
        float var  = fmaxf(Q / cnt - mean * mean, 0.f);
        smean[t] = mean;
        srstd[t] = rsqrtf(var + 1e-5f);
    }
    __syncthreads();

    const float m0 = smean[lane];
    const float m1 = smean[lane + 32];
    const float r0 = srstd[lane];
    const float r1 = srstd[lane + 32];

    const float* E = emb + (size_t)row * 64;
    float e0 = E[lane], e1 = E[lane + 32];
    float m = (j < nb[b]) ? 1.f : 0.f;
    float n0 = (e0 - m0) * r0 * m;
    float n1 = (e1 - m1) * r1 * m;

    const int pf0 = phi(lane), pf1 = phi(lane + 32);
    g_Ep   [(size_t)row * 64 + pf0] = e0;
    g_Ep   [(size_t)row * 64 + pf1] = e1;
    g_embnP[(size_t)row * 64 + pf0] = n0;
    g_embnP[(size_t)row * 64 + pf1] = n1;
    etile[w][lane] = e0;  etile[w][lane + 32] = e1;
    ntile[w][lane] = n0;  ntile[w][lane + 32] = n1;

    float sq = e0 * e0 + e1 * e1;
    #pragma unroll
    for (int o = 16; o; o >>= 1) sq += __shfl_down_sync(0xffffffffu, sq, o);
    if (lane == 0) g_sq[row] = sq;

    __syncthreads();

    const int j0 = (blockIdx.x * 8) % N;
    const int b0 = (blockIdx.x * 8) / N;
    const int nbk = (j0 & 63) >> 3;
    const size_t tbase = ((size_t)(b0 * (N >> 6) + (j0 >> 6))) * 4096;

    #pragma unroll
    for (int it = 0; it < 2; it++) {
        const int idx = t + it * 256;
        const int seg = idx >> 6;
        const int sl  = idx & 63;
        const int lp = sl >> 1, half = sl & 1;
        const int g = lp >> 2, q = lp & 3;
        g_EjF[tbase + (size_t)(nbk * 8 + seg) * 64 + sl] =
            __uint_as_float(f2tf(etile[g][seg * 8 + half * 4 + q]));
        g_EnF[tbase + (size_t)(seg * 8 + nbk) * 64 + sl] =
            __uint_as_float(f2tf(ntile[half * 4 + q][seg * 8 + g]));
    }
}

// ---------------- Kernel 2: fused Gram -> eltwise -> adj/deg -> SpMM -> MLP ----------------
#define SSS 72
#define SX2 136
#define OFF_EJ  0u
#define OFF_EN  32768u
#define OFF_SS  65536u
#define OFF_SQ  (65536u + 64u * SSS * 4u)
#define OFF_DG  (OFF_SQ + 512u)
#define SMEM_KADJ (OFF_DG + 256u)
// MLP tail overlays: sx [64][SX2] at 0 (34816B, over dead EJ/EN); sb1/sb2 at OFF_SQ.

__global__ __launch_bounds__(256, 2) void kadj(
    const float* __restrict__ adj_in,
    const int* __restrict__ nb, const float* __restrict__ sigma_p,
    const float* __restrict__ cw, float* __restrict__ adj_out,
    const uint4* __restrict__ W1f, const float* __restrict__ b1,
    const uint4* __restrict__ W2f, const float* __restrict__ b2,
    float* __restrict__ out_emb, int N)
{
    extern __shared__ char smc[];
    uint32_t* sS   = (uint32_t*)(smc + OFF_SS);
    float*    ssqj = (float*)(smc + OFF_SQ);
    float*    sdeg = (float*)(smc + OFF_DG);

    const int b = blockIdx.y;
    const int ibase = blockIdx.x * 64;
    const int t = threadIdx.x;
    const int w = t >> 5, lane = t & 31;
    const int rowb = (w >> 1) * 16, colb = (w & 1) * 32;
    const int g = lane >> 2, tg = lane & 3;
    const int p0 = (((2 * tg) & 3) << 1) | ((2 * tg) >> 2);
    const int p1 = (((2 * tg + 1) & 3) << 1) | ((2 * tg + 1) >> 2);

    const float inv_sigma = 1.0f / sigma_p[0];
    const float w0 = cw[0], w1 = cw[1];
    const int nbv = nb[b];

    const float* Ep   = g_Ep    + (size_t)b * N * 64;
    const float* EnP  = g_embnP + (size_t)b * N * 64;
    const float* SQ   = g_sq    + b * N;
    const float* Ain  = adj_in  + (size_t)b * N * N;
    float*       Aout = adj_out + (size_t)b * N * N;

    uint32_t u_base;
    asm("{ .reg .u64 t; cvta.to.shared.u64 t, %1; cvt.u32.u64 %0, t; }"
        : "=r"(u_base) : "l"(smc));

    const int gi0 = ibase + rowb + g;
    const int gi1 = gi0 + 8;

    auto stage = [&](int pb, int jt) {
        const size_t tIdx = (size_t)(b * (N >> 6) + (jt >> 6)) * 4096;
        const float* srcEj = g_EjF + tIdx;
        const float* srcEn = g_EnF + tIdx;
        #pragma unroll
        for (int k = 0; k < 4; k++) {
            const int c = t + k * 256;
            cpa16(u_base + OFF_EJ + pb * 16384u + c * 16u, srcEj + c * 4);
            cpa16(u_base + OFF_EN + pb * 16384u + c * 16u, srcEn + c * 4);
        }
        if (t < 16)
            cpa16(u_base + OFF_SQ + pb * 256u + t * 16u, &SQ[jt + t * 4]);
    };

    stage(0, 0);
    asm volatile("cp.async.commit_group;\n");

    uint32_t aF[8][4];
    #pragma unroll
    for (int ks = 0; ks < 8; ks++) {
        float2 q0 = *(const float2*)&Ep[(size_t)gi0 * 64 + ks * 8 + 2 * tg];
        float2 q1 = *(const float2*)&Ep[(size_t)gi1 * 64 + ks * 8 + 2 * tg];
        aF[ks][0] = f2tf(q0.x);
        aF[ks][1] = f2tf(q1.x);
        aF[ks][2] = f2tf(q0.y);
        aF[ks][3] = f2tf(q1.y);
    }
    const float sqi0 = SQ[gi0];
    const float sqi1 = SQ[gi1];
    if (t < 64) sdeg[t] = 0.f;
    const float mi0 = (gi0 < nbv) ? 1.f : 0.f;
    const float mi1 = (gi1 < nbv) ? 1.f : 0.f;

    float opa[4][4];
    #pragma unroll
    for (int n = 0; n < 4; n++)
        #pragma unroll
        for (int k = 0; k < 4; k++) opa[n][k] = 0.f;
    float dg0 = 0.f, dg1 = 0.f;

    asm volatile("cp.async.wait_group 0;\n");
    __syncthreads();

    int pb = 0;
    for (int jt = 0; jt < N; jt += 64, pb ^= 1) {
        if (jt + 64 < N) stage(pb ^ 1, jt + 64);
        asm volatile("cp.async.commit_group;\n");

        float2 a01[4], a23[4];
        #pragma unroll
        for (int nt = 0; nt < 4; nt++) {
            const int gj = jt + colb + nt * 8 + 2 * tg;
            a01[nt] = *(const float2*)&Ain[(size_t)gi0 * N + gj];
            a23[nt] = *(const float2*)&Ain[(size_t)gi1 * N + gj];
        }

        const uint2* Ej = (const uint2*)(smc + OFF_EJ + pb * 16384u);
        const uint2* En = (const uint2*)(smc + OFF_EN + pb * 16384u);
        const float* sqj = ssqj + pb * 64;

        float S[4][4];
        #pragma unroll
        for (int n = 0; n < 4; n++)
            #pragma unroll
            for (int k = 0; k < 4; k++) S[n][k] = 0.f;

        #pragma unroll
        for (int nt = 0; nt < 4; nt++) {
            const int jb = (w & 1) * 4 + nt;
            #pragma unroll
            for (int ks = 0; ks < 8; ks++) {
                uint2 bv = Ej[(jb * 8 + ks) * 32 + lane];
                MMA_TF32(S[nt], aF[ks][0], aF[ks][1], aF[ks][2], aF[ks][3], bv.x, bv.y);
            }
        }

        #pragma unroll
        for (int nt = 0; nt < 4; nt++) {
            const int jl = colb + nt * 8 + 2 * tg;
            const int gj = jt + jl;
            const float sqj0 = sqj[jl], sqj1 = sqj[jl + 1];
            const float mj0 = (gj     < nbv) ? 1.f : 0.f;
            const float mj1 = (gj + 1 < nbv) ? 1.f : 0.f;

            float v00 = (w0 * a01[nt].x + w1 * __expf(-fmaxf(sqi0 + sqj0 - 2.f * S[nt][0], 0.f) * inv_sigma)) * (mi0 * mj0);
            float v01 = (w0 * a01[nt].y + w1 * __expf(-fmaxf(sqi0 + sqj1 - 2.f * S[nt][1], 0.f) * inv_sigma)) * (mi0 * mj1);
            float v10 = (w0 * a23[nt].x + w1 * __expf(-fmaxf(sqi1 + sqj0 - 2.f * S[nt][2], 0.f) * inv_sigma)) * (mi1 * mj0);
            float v11 = (w0 * a23[nt].y + w1 * __expf(-fmaxf(sqi1 + sqj1 - 2.f * S[nt][3], 0.f) * inv_sigma)) * (mi1 * mj1);

            dg0 += v00 + v01;
            dg1 += v10 + v11;

            *(float2*)&Aout[(size_t)gi0 * N + gj] = make_float2(v00, v01);
            *(float2*)&Aout[(size_t)gi1 * N + gj] = make_float2(v10, v11);

            const int cb = colb + nt * 8;
            sS[(rowb + g)     * SSS + cb + p0] = f2tf(v00);
            sS[(rowb + g)     * SSS + cb + p1] = f2tf(v01);
            sS[(rowb + g + 8) * SSS + cb + p0] = f2tf(v10);
            sS[(rowb + g + 8) * SSS + cb + p1] = f2tf(v11);
        }
        asm volatile("bar.sync %0, 64;" :: "r"(1 + (w >> 1)) : "memory");

        #pragma unroll
        for (int ks = 0; ks < 8; ks++) {
            uint2 A02 = *(const uint2*)&sS[(rowb + g)     * SSS + ks * 8 + 2 * tg];
            uint2 A13 = *(const uint2*)&sS[(rowb + g + 8) * SSS + ks * 8 + 2 * tg];
            #pragma unroll
            for (int nt = 0; nt < 4; nt++) {
                const int fb = (w & 1) * 4 + nt;
                uint2 bv = En[(fb * 8 + ks) * 32 + lane];
                MMA_TF32(opa[nt], A02.x, A13.x, A02.y, A13.y, bv.x, bv.y);
            }
        }

        asm volatile("cp.async.wait_group 0;\n");
        __syncthreads();
    }

    // ---- deg reduce (sdeg finalized) ----
    dg0 += __shfl_xor_sync(0xffffffffu, dg0, 1);
    dg0 += __shfl_xor_sync(0xffffffffu, dg0, 2);
    dg1 += __shfl_xor_sync(0xffffffffu, dg1, 1);
    dg1 += __shfl_xor_sync(0xffffffffu, dg1, 2);
    if (tg == 0) {
        atomicAdd(&sdeg[rowb + g], dg0);
        atomicAdd(&sdeg[rowb + g + 8], dg1);
    }
    __syncthreads();

    // ================= fused MLP tail (this CTA's 64 nodes) =================
    float* sx  = (float*)smc;                   // [64][SX2], overlays dead EJ/EN
    float* sb1 = (float*)(smc + OFF_SQ);        // overlays dead ssqj
    float* sb2 = (float*)(smc + OFF_SQ + 256u);

    if (t < 64) { sb1[t] = b1[t]; sb2[t] = b2[t]; }

    // op_adj half of x1 from registers (phi cols)
    #pragma unroll
    for (int nt = 0; nt < 4; nt++) {
        const int base = 64 + colb + nt * 8;
        sx[(rowb + g)     * SX2 + base + p0] = opa[nt][0];
        sx[(rowb + g)     * SX2 + base + p1] = opa[nt][1];
        sx[(rowb + g + 8) * SX2 + base + p0] = opa[nt][2];
        sx[(rowb + g + 8) * SX2 + base + p1] = opa[nt][3];
    }
    // deg*embn half of x1
    for (int idx = t; idx < 1024; idx += 256) {
        const int node = idx >> 4, c = (idx & 15) << 2;
        const float dgv = sdeg[node];
        float4 v = *(const float4*)&EnP[(size_t)(ibase + node) * 64 + c];
        v.x *= dgv; v.y *= dgv; v.z *= dgv; v.w *= dgv;
        *(float4*)&sx[node * SX2 + c] = v;
    }
    __syncthreads();

    // ---- MLP stage 1: upd = x1 @ W1 (weights via LDG, split hh+lh+hl) ----
    float acc1[4][4];
    #pragma unroll
    for (int n = 0; n < 4; n++)
        #pragma unroll
        for (int k = 0; k < 4; k++) acc1[n][k] = 0.f;

    #pragma unroll
    for (int ks = 0; ks < 16; ks++) {
        float2 A0 = *(const float2*)&sx[(rowb + g)     * SX2 + ks * 8 + 2 * tg];
        float2 A1 = *(const float2*)&sx[(rowb + g + 8) * SX2 + ks * 8 + 2 * tg];
        uint32_t ah[4], al[4];
        split_tf(A0.x, ah[0], al[0]);
        split_tf(A1.x, ah[1], al[1]);
        split_tf(A0.y, ah[2], al[2]);
        split_tf(A1.y, ah[3], al[3]);
        #pragma unroll
        for (int nt = 0; nt < 4; nt++) {
            const int nf = (colb >> 3) + nt;
            uint4 wv = __ldg(&W1f[(nf * 16 + ks) * 32 + lane]);
            MMA_TF32(acc1[nt], ah[0], ah[1], ah[2], ah[3], wv.x, wv.y);
            MMA_TF32(acc1[nt], al[0], al[1], al[2], al[3], wv.x, wv.y);
            MMA_TF32(acc1[nt], ah[0], ah[1], ah[2], ah[3], wv.z, wv.w);
        }
    }
    __syncthreads();

    // build x2 = [emb_in (phi), upd+b1 (phi)]
    for (int idx = t; idx < 1024; idx += 256) {
        const int node = idx >> 4, c = (idx & 15) << 2;
        *(float4*)&sx[node * SX2 + c] = *(const float4*)&Ep[(size_t)(ibase + node) * 64 + c];
    }
    #pragma unroll
    for (int nt = 0; nt < 4; nt++) {
        const int f0 = colb + nt * 8 + 2 * tg;
        const int base = 64 + colb + nt * 8;
        sx[(rowb + g)     * SX2 + base + p0] = acc1[nt][0] + sb1[f0];
        sx[(rowb + g)     * SX2 + base + p1] = acc1[nt][1] + sb1[f0 + 1];
        sx[(rowb + g + 8) * SX2 + base + p0] = acc1[nt][2] + sb1[f0];
        sx[(rowb + g + 8) * SX2 + base + p1] = acc1[nt][3] + sb1[f0 + 1];
    }
    __syncthreads();

    // ---- MLP stage 2: out = relu(x2 @ W2 + b2) ----
    float acc2[4][4];
    #pragma unroll
    for (int n = 0; n < 4; n++)
        #pragma unroll
        for (int k = 0; k < 4; k++) acc2[n][k] = 0.f;

    #pragma unroll
    for (int ks = 0; ks < 16; ks++) {
        float2 A0 = *(const float2*)&sx[(rowb + g)     * SX2 + ks * 8 + 2 * tg];
        float2 A1 = *(const float2*)&sx[(rowb + g + 8) * SX2 + ks * 8 + 2 * tg];
        uint32_t ah[4], al[4];
        split_tf(A0.x, ah[0], al[0]);
        split_tf(A1.x, ah[1], al[1]);
        split_tf(A0.y, ah[2], al[2]);
        split_tf(A1.y, ah[3], al[3]);
        #pragma unroll
        for (int nt = 0; nt < 4; nt++) {
            const int nf = (colb >> 3) + nt;
            uint4 wv = __ldg(&W2f[(nf * 16 + ks) * 32 + lane]);
            MMA_TF32(acc2[nt], ah[0], ah[1], ah[2], ah[3], wv.x, wv.y);
            MMA_TF32(acc2[nt], al[0], al[1], al[2], al[3], wv.x, wv.y);
            MMA_TF32(acc2[nt], ah[0], ah[1], ah[2], ah[3], wv.z, wv.w);
        }
    }

    float* Oemb = out_emb + (size_t)b * N * 64;
    #pragma unroll
    for (int nt = 0; nt < 4; nt++) {
        const int f0 = colb + nt * 8 + 2 * tg;
        float o00 = fmaxf(acc2[nt][0] + sb2[f0],     0.f);
        float o01 = fmaxf(acc2[nt][1] + sb2[f0 + 1], 0.f);
        float o10 = fmaxf(acc2[nt][2] + sb2[f0],     0.f);
        float o11 = fmaxf(acc2[nt][3] + sb2[f0 + 1], 0.f);
        *(float2*)&Oemb[(size_t)gi0 * 64 + f0] = make_float2(o00, o01);
        *(float2*)&Oemb[(size_t)gi1 * 64 + f0] = make_float2(o10, o11);
    }
}

// ---------------- launch ----------------
extern "C" void kernel_launch(void* const* d_in, const int* in_sizes, int n_in,
                              void* d_out, int out_size)
{
    const float* emb_in = (const float*)d_in[0];
    const float* adj_in = (const float*)d_in[1];
    // d_in[2] adj_mask: unused (recomputed from batch_nb_nodes)
    const int*   nbp    = (const int*)d_in[3];
    const float* sigma  = (const float*)d_in[4];
    const float* cw     = (const float*)d_in[5];
    const float* convW  = (const float*)d_in[6];
    const float* convb  = (const float*)d_in[7];
    const float* nuW    = (const float*)d_in[8];
    const float* nub    = (const float*)d_in[9];

    const int B = in_sizes[3];
    const int N = in_sizes[0] / (B * 64);

    float* out_emb = (float*)d_out;                    // (B,N,64)
    float* out_adj = out_emb + (size_t)B * N * 64;     // (B,N,N)

    uint4 *p_W1f, *p_W2f;
    cudaGetSymbolAddress((void**)&p_W1f, g_W1f);
    cudaGetSymbolAddress((void**)&p_W2f, g_W2f);

    kstat1<<<dim3(B, 10), 256>>>(emb_in, convW, nuW, N);
    knorm2<<<(B * N) / 8, 256>>>(emb_in, nbp, N);

    cudaFuncSetAttribute(kadj, cudaFuncAttributeMaxDynamicSharedMemorySize, (int)SMEM_KADJ);
    kadj<<<dim3(N / 64, B), 256, SMEM_KADJ>>>(adj_in, nbp, sigma, cw, out_adj,
                                              p_W1f, convb, p_W2f, nub, out_emb, N);
}